// round 13
// baseline (speedup 1.0000x reference)
#include <cuda_runtime.h>
#include <math.h>

#define BB 64
#define FF 512
#define EE 256
#define HH 8
#define DD 32
#define LL 4

// Precomputed collapsed vectors (device globals: no allocation allowed)
__device__ float g_kw[EE];   // emb_w @ k_w
__device__ float g_vw[EE];   // emb_w @ v_w
__device__ float g_vb[EE];   // emb_b @ v_w + v_b
__device__ float g_qv[EE];   // emb_b @ q_w + q_b

__device__ __forceinline__ float ex2f(float x) {
    float y;
    asm("ex2.approx.ftz.f32 %0, %1;" : "=f"(y) : "f"(x));
    return y;
}

// ---------------------------------------------------------------------------
// Kernel A (r4/r11-proven): 4 vector-matrix products, each 256-dot split
// across 8 warps. grid = 32 (4 matrices x 8 col-groups), 256 threads.
// Extra: warp 1 L2-prefetches this block's 4KB slice of features so kernel
// B's feature loads hit L2 instead of cold DRAM (fire-and-forget, off the
// critical path).
// ---------------------------------------------------------------------------
__global__ void __launch_bounds__(256)
precompute_kernel(const float* __restrict__ emb_w,
                  const float* __restrict__ emb_b,
                  const float* __restrict__ q_w,
                  const float* __restrict__ q_b,
                  const float* __restrict__ k_w,
                  const float* __restrict__ v_w,
                  const float* __restrict__ v_b,
                  const float* __restrict__ features) {
    const int m     = blockIdx.x >> 3;          // 0:kw 1:vw 2:vb 3:qv
    const int grp   = blockIdx.x & 7;           // column group (32 cols)
    const int lane  = threadIdx.x & 31;
    const int chunk = threadIdx.x >> 5;         // row chunk == warp id
    const int col   = grp * 32 + lane;

    // L2-prefetch features: block i covers bytes [i*4KB, (i+1)*4KB)
    if (chunk == 1) {
        const char* fp = reinterpret_cast<const char*>(features)
                       + blockIdx.x * 4096 + lane * 128;
        asm volatile("prefetch.global.L2 [%0];" :: "l"(fp));
    }

    const float* vecsrc = (m <= 1) ? emb_w : emb_b;
    const float* mat    = (m == 0) ? k_w : (m == 3 ? q_w : v_w);

    float ev = vecsrc[chunk * 32 + lane];
    const float* mp = mat + (chunk * 32) * EE + col;

    float acc = 0.f;
    #pragma unroll
    for (int e = 0; e < 32; e++)
        acc = fmaf(__shfl_sync(0xffffffffu, ev, e), mp[e * EE], acc);

    __shared__ float s[8][32];
    s[chunk][lane] = acc;
    __syncthreads();

    if (threadIdx.x < 32) {
        float a = 0.f;
        #pragma unroll
        for (int r = 0; r < 8; r++) a += s[r][lane];
        if (m == 2) a += v_b[col];
        if (m == 3) a += q_b[col];
        float* dst = (m == 0) ? g_kw : (m == 1) ? g_vw : (m == 2) ? g_vb : g_qv;
        dst[col] = a;
    }
}

// ---------------------------------------------------------------------------
// Kernel B (r11-proven): grid = 64, 256 threads = 8 warps = 8 heads.
// No occupancy cap -> no spills (48-50 regs). Features via 4x LDG.128
// (L2-warm thanks to kernel A's prefetch) + 5 head-vector loads upfront;
// one combined 7-value butterfly; L=4 recursion with 4-way ILP; STG.128
// epilogue.
// ---------------------------------------------------------------------------
__global__ void __launch_bounds__(256, 1)
attn_kernel(const float* __restrict__ features,
            const float* __restrict__ attn_w,
            const float* __restrict__ attn_b,
            float* __restrict__ out) {
    __shared__ float s_ox[HH], s_hc[HH];

    const int b    = blockIdx.x;
    const int t    = threadIdx.x;
    const int warp = t >> 5;
    const int lane = t & 31;

    // ---- all loads issued up front ----
    const float4* xb4 = reinterpret_cast<const float4*>(features + b * FF);
    float4 v0 = xb4[lane +  0];
    float4 v1 = xb4[lane + 32];
    float4 v2 = xb4[lane + 64];
    float4 v3 = xb4[lane + 96];

    const int hi = warp * DD + lane;
    float kw = g_kw[hi];
    float vw = g_vw[hi];
    float vb = g_vb[hi];
    float qv = g_qv[hi];
    float aw = attn_w[hi];
    float ab = attn_b[0];

    float xr[16];
    xr[0]=v0.x; xr[1]=v0.y; xr[2]=v0.z; xr[3]=v0.w;
    xr[4]=v1.x; xr[5]=v1.y; xr[6]=v1.z; xr[7]=v1.w;
    xr[8]=v2.x; xr[9]=v2.y; xr[10]=v2.z; xr[11]=v2.w;
    xr[12]=v3.x; xr[13]=v3.y; xr[14]=v3.z; xr[15]=v3.w;

    // ---- local stats ----
    float Sl = 0.f, xmax = -1e30f, xmin = 1e30f;
    #pragma unroll
    for (int i = 0; i < 16; i++) {
        Sl += xr[i];
        xmax = fmaxf(xmax, xr[i]);
        xmin = fminf(xmin, xr[i]);
    }

    // ---- head scalars (per-lane products) ----
    const float scale = 0.17677669529663687f;      // 1/sqrt(32)
    float A0 = qv * kw, P = vw * kw, R = vb * kw, VA = vw * aw, VB = vb * aw;

    // ---- one combined butterfly: max/min + 5 dot reductions ----
    #pragma unroll
    for (int o = 16; o > 0; o >>= 1) {
        xmax = fmaxf(xmax, __shfl_xor_sync(0xffffffffu, xmax, o));
        xmin = fminf(xmin, __shfl_xor_sync(0xffffffffu, xmin, o));
        A0  += __shfl_xor_sync(0xffffffffu, A0, o);
        P   += __shfl_xor_sync(0xffffffffu, P,  o);
        R   += __shfl_xor_sync(0xffffffffu, R,  o);
        VA  += __shfl_xor_sync(0xffffffffu, VA, o);
        VB  += __shfl_xor_sync(0xffffffffu, VB, o);
    }
    A0 *= scale; P *= scale; R *= scale;

    // ---- L-step scalar softmax recursion: 4-way ILP, no live w[] array ----
    const float L2E = 1.4426950408889634f;
    float alpha = A0;
    float m = 0.f;
    #pragma unroll
    for (int it = 0; it < LL; it++) {
        float a2 = alpha * L2E;
        float M2 = (alpha >= 0.f) ? a2 * xmax : a2 * xmin;   // exact max logit
        float swa = 0.f, swb = 0.f, swc = 0.f, swd = 0.f;
        float sxa = 0.f, sxb = 0.f, sxc = 0.f, sxd = 0.f;
        #pragma unroll
        for (int i = 0; i < 4; i++) {
            float wa = ex2f(fmaf(a2, xr[4*i+0], -M2));
            float wb = ex2f(fmaf(a2, xr[4*i+1], -M2));
            float wc = ex2f(fmaf(a2, xr[4*i+2], -M2));
            float wd = ex2f(fmaf(a2, xr[4*i+3], -M2));
            swa += wa; sxa = fmaf(xr[4*i+0], wa, sxa);
            swb += wb; sxb = fmaf(xr[4*i+1], wb, sxb);
            swc += wc; sxc = fmaf(xr[4*i+2], wc, sxc);
            swd += wd; sxd = fmaf(xr[4*i+3], wd, sxd);
        }
        float sw  = (swa + swb) + (swc + swd);
        float sxw = (sxa + sxb) + (sxc + sxd);
        #pragma unroll
        for (int o = 16; o > 0; o >>= 1) {
            sw  += __shfl_xor_sync(0xffffffffu, sw,  o);
            sxw += __shfl_xor_sync(0xffffffffu, sxw, o);
        }
        m = __fdividef(sxw, sw);
        alpha = fmaf(m, P, R);
    }

    // ---- deferred sum butterfly (off the recursion path) ----
    float S = Sl;
    #pragma unroll
    for (int o = 16; o > 0; o >>= 1)
        S += __shfl_xor_sync(0xffffffffu, S, o);

    if (lane == 0) {
        s_ox[warp] = fmaf(m, VA, VB);                          // Qc contribution
        s_hc[warp] = fmaf(S - m, VA, (float)(FF - 1) * VB);    // (v_sum - Qc)
    }
    __syncthreads();   // single block sync

    float ox = ab, cc = ab;
    #pragma unroll
    for (int hh = 0; hh < HH; hh++) { ox += s_ox[hh]; cc += s_hc[hh]; }

    // ---- epilogue: one STG.128 per thread (values constant across f) ----
    float val = (t < 128) ? ox : cc;
    float4* dst = reinterpret_cast<float4*>(
        (t < 128) ? (out + b * FF) : (out + BB * FF + b * FF));
    dst[t & 127] = make_float4(val, val, val, val);
}

extern "C" void kernel_launch(void* const* d_in, const int* in_sizes, int n_in,
                              void* d_out, int out_size) {
    const float* features = (const float*)d_in[0];
    const float* emb_w    = (const float*)d_in[1];
    const float* emb_b    = (const float*)d_in[2];
    const float* q_w      = (const float*)d_in[3];
    const float* q_b      = (const float*)d_in[4];
    const float* k_w      = (const float*)d_in[5];
    // d_in[6] = k_b: cancels in softmax, unused
    const float* v_w      = (const float*)d_in[7];
    const float* v_b      = (const float*)d_in[8];
    const float* attn_w   = (const float*)d_in[9];
    const float* attn_b   = (const float*)d_in[10];
    float* out = (float*)d_out;

    precompute_kernel<<<32, 256>>>(emb_w, emb_b, q_w, q_b, k_w, v_w, v_b,
                                   features);
    attn_kernel<<<BB, 256>>>(features, attn_w, attn_b, out);
}